// round 2
// baseline (speedup 1.0000x reference)
#include <cuda_runtime.h>
#include <math.h>

#define BATCH 32
#define NTOK  4096
#define DIM   256
#define M_TOT 672

// ---------------- scratch ----------------
__device__ float g_Qp[M_TOT * DIM];
__device__ float g_c [M_TOT];
__device__ float g_S [(long)BATCH * M_TOT * NTOK];
__device__ float g_H [BATCH * M_TOT * DIM];
__device__ float g_part[BATCH * 16 * DIM];
__device__ float g_cnt [BATCH * 16];

// ---------------- prep: Q' = (codes@Wq^T+bq)@Wk / 16, c = q.bk/16 ----------------
__global__ __launch_bounds__(256)
void prep_q(const float* __restrict__ cat, const float* __restrict__ typ,
            const float* __restrict__ var, const float* __restrict__ sp,
            const float* __restrict__ Wcat, const float* __restrict__ bcat,
            const float* __restrict__ Wtype, const float* __restrict__ btype,
            const float* __restrict__ Wvar, const float* __restrict__ bvar,
            const float* __restrict__ Wsp, const float* __restrict__ bsp,
            const float* __restrict__ Wk, const float* __restrict__ bk,
            float* __restrict__ Qp, float* __restrict__ cvec)
{
    int m = blockIdx.x;
    const float* codes; const float* Wq; const float* bq;
    if (m < 16)       { codes = cat + m * DIM;         Wq = Wcat;  bq = bcat; }
    else if (m < 144) { codes = typ + (m - 16) * DIM;  Wq = Wtype; bq = btype; }
    else if (m < 656) { codes = var + (m - 144) * DIM; Wq = Wvar;  bq = bvar; }
    else              { codes = sp + (m - 656) * DIM;  Wq = Wsp;   bq = bsp; }

    __shared__ float cs[DIM], qs[DIM], red[256];
    int t = threadIdx.x;
    cs[t] = codes[t];
    __syncthreads();

    int w = t >> 5, l = t & 31;
    for (int j = w; j < DIM; j += 8) {
        const float* wr = Wq + j * DIM;
        float s = 0.f;
        #pragma unroll
        for (int i = 0; i < 8; i++) s += wr[l + 32 * i] * cs[l + 32 * i];
        #pragma unroll
        for (int o = 16; o > 0; o >>= 1) s += __shfl_xor_sync(0xffffffffu, s, o);
        if (l == 0) qs[j] = s + bq[j];
    }
    __syncthreads();

    float a = 0.f;
    for (int j = 0; j < DIM; j++) a += qs[j] * Wk[j * DIM + t];
    Qp[m * DIM + t] = a * 0.0625f;

    red[t] = qs[t] * bk[t];
    __syncthreads();
    for (int s = 128; s > 0; s >>= 1) { if (t < s) red[t] += red[t + s]; __syncthreads(); }
    if (t == 0) cvec[m] = red[0] * 0.0625f;
}

// ---------------- tiled fp32 GEMM (BM=BN=128, BK=8, 256 threads, 8x8 microtile) ----------------
// BT=true : B(k,n) = Bm[n*ldb + k]   (X^T, for logits)
// BT=false: B(k,n) = Bm[k*ldb + n]   (for H = G@X)
// EPI: fused +c[m], clip [-50,50], mask->-50
template<bool BT, bool EPI>
__global__ __launch_bounds__(256)
void gemm_kernel(const float* __restrict__ A, const float* __restrict__ Bm,
                 float* __restrict__ C, int M, int N, int K,
                 int lda, int ldb, int ldc,
                 long sA, long sB, long sC,
                 const float* __restrict__ cvec,
                 const unsigned char* __restrict__ mask)
{
    const int BM = 128, BN = 128, BK = 8;
    __shared__ __align__(16) float As[BK][BM + 4];
    __shared__ __align__(16) float Bs[BK][BN + 4];

    int b = blockIdx.z;
    A  += sA * (long)b;
    Bm += sB * (long)b;
    C  += sC * (long)b;
    const unsigned char* mrow = EPI ? (mask + (long)b * N) : (const unsigned char*)0;

    int t = threadIdx.x;
    int m0 = blockIdx.y * BM, n0 = blockIdx.x * BN;
    int tm = (t >> 4) * 8;       // 0..120
    int tn = (t & 15) * 4;       // 0..60 ; second chunk at tn+64

    float4 aReg, bReg;

    auto loadA = [&](int kt) {
        int row = t >> 1, kq = t & 1;
        int gm = m0 + row;
        aReg = make_float4(0.f, 0.f, 0.f, 0.f);
        if (gm < M) aReg = *(const float4*)(A + (long)gm * lda + kt * BK + kq * 4);
    };
    auto loadB = [&](int kt) {
        if (BT) {
            int n = t >> 1, kq = t & 1;
            bReg = *(const float4*)(Bm + (long)(n0 + n) * ldb + kt * BK + kq * 4);
        } else {
            int k = t >> 5, nq = t & 31;
            bReg = *(const float4*)(Bm + (long)(kt * BK + k) * ldb + n0 + nq * 4);
        }
    };
    auto storeA = [&]() {
        int row = t >> 1, kq = t & 1;
        As[kq * 4 + 0][row] = aReg.x; As[kq * 4 + 1][row] = aReg.y;
        As[kq * 4 + 2][row] = aReg.z; As[kq * 4 + 3][row] = aReg.w;
    };
    auto storeB = [&]() {
        if (BT) {
            int n = t >> 1, kq = t & 1;
            Bs[kq * 4 + 0][n] = bReg.x; Bs[kq * 4 + 1][n] = bReg.y;
            Bs[kq * 4 + 2][n] = bReg.z; Bs[kq * 4 + 3][n] = bReg.w;
        } else {
            int k = t >> 5, nq = t & 31;
            *(float4*)&Bs[k][nq * 4] = bReg;
        }
    };

    float acc[8][8] = {};
    int KT = K / BK;
    loadA(0); loadB(0);
    for (int kt = 0; kt < KT; ++kt) {
        __syncthreads();
        storeA(); storeB();
        __syncthreads();
        if (kt + 1 < KT) { loadA(kt + 1); loadB(kt + 1); }
        #pragma unroll
        for (int k = 0; k < BK; k++) {
            float4 a0 = *(const float4*)&As[k][tm];
            float4 a1 = *(const float4*)&As[k][tm + 4];
            float4 b0 = *(const float4*)&Bs[k][tn];
            float4 b1 = *(const float4*)&Bs[k][tn + 64];
            float ar[8] = {a0.x,a0.y,a0.z,a0.w,a1.x,a1.y,a1.z,a1.w};
            float br[8] = {b0.x,b0.y,b0.z,b0.w,b1.x,b1.y,b1.z,b1.w};
            #pragma unroll
            for (int i = 0; i < 8; i++)
                #pragma unroll
                for (int j = 0; j < 8; j++)
                    acc[i][j] += ar[i] * br[j];
        }
    }

    #pragma unroll
    for (int i = 0; i < 8; i++) {
        int gm = m0 + tm + i;
        if (gm >= M) continue;
        float cv = EPI ? cvec[gm] : 0.f;
        float* crow = C + (long)gm * ldc + n0;
        #pragma unroll
        for (int half = 0; half < 2; half++) {
            int base = tn + half * 64;
            float4 v;
            float* pv = &v.x;
            #pragma unroll
            for (int q = 0; q < 4; q++) {
                float x = acc[i][half * 4 + q];
                if (EPI) {
                    x += cv;
                    x = fminf(fmaxf(x, -50.f), 50.f);
                    if (!mrow[n0 + base + q]) x = -50.f;
                }
                pv[q] = x;
            }
            *(float4*)(crow + base) = v;
        }
    }
}

// ---------------- softmax over rows of 4096 ----------------
__global__ __launch_bounds__(256)
void softmax_rows(float* __restrict__ S)
{
    long row = blockIdx.x;
    float* p = S + row * (long)NTOK;
    int t = threadIdx.x;
    float v[16];
    float mx = -1e30f;
    #pragma unroll
    for (int i = 0; i < 16; i++) { v[i] = p[t + 256 * i]; mx = fmaxf(mx, v[i]); }
    __shared__ float red[256];
    red[t] = mx; __syncthreads();
    for (int s = 128; s > 0; s >>= 1) { if (t < s) red[t] = fmaxf(red[t], red[t + s]); __syncthreads(); }
    mx = red[0]; __syncthreads();
    float sum = 0.f;
    #pragma unroll
    for (int i = 0; i < 16; i++) { v[i] = expf(v[i] - mx); sum += v[i]; }
    red[t] = sum; __syncthreads();
    for (int s = 128; s > 0; s >>= 1) { if (t < s) red[t] += red[t + s]; __syncthreads(); }
    float inv = 1.0f / red[0];
    #pragma unroll
    for (int i = 0; i < 16; i++) p[t + 256 * i] = v[i] * inv;
}

// ---------------- masked position pooling partials ----------------
__global__ __launch_bounds__(256)
void pospool_partial(const float* __restrict__ pos, const unsigned char* __restrict__ mask,
                     float* __restrict__ part, float* __restrict__ cnt)
{
    int s = blockIdx.x, b = blockIdx.y;
    int t = threadIdx.x;
    const float* P = pos + ((long)b * NTOK + s * 256) * DIM;
    const unsigned char* M = mask + (long)b * NTOK + s * 256;
    float acc = 0.f, c = 0.f;
    for (int n = 0; n < 256; n++) {
        float mm = M[n] ? 1.f : 0.f;
        c += mm;
        acc += mm * P[(long)n * DIM + t];
    }
    part[((long)b * 16 + s) * DIM + t] = acc;
    if (t == 0) cnt[b * 16 + s] = c;
}

// ---------------- per-batch tail ----------------
__device__ __forceinline__ float blk_sum(float v, float* red, int t)
{
    __syncthreads();
    red[t] = v; __syncthreads();
    for (int s = 128; s > 0; s >>= 1) { if (t < s) red[t] += red[t + s]; __syncthreads(); }
    float r = red[0]; __syncthreads();
    return r;
}
__device__ __forceinline__ float blk_max(float v, float* red, int t)
{
    __syncthreads();
    red[t] = v; __syncthreads();
    for (int s = 128; s > 0; s >>= 1) { if (t < s) red[t] = fmaxf(red[t], red[t + s]); __syncthreads(); }
    float r = red[0]; __syncthreads();
    return r;
}

__device__ void softmax_sparsify(float* a, int len, float thr, float* red, int t)
{
    float m = -1e30f;
    for (int i = t; i < len; i += 256) m = fmaxf(m, a[i]);
    m = blk_max(m, red, t);
    float s = 0.f;
    for (int i = t; i < len; i += 256) { float e = expf(a[i] - m); a[i] = e; s += e; }
    s = blk_sum(s, red, t);
    float inv = 1.f / s;
    float s2 = 0.f;
    for (int i = t; i < len; i += 256) { float p = a[i] * inv; p = (p > thr) ? p : 0.f; a[i] = p; s2 += p; }
    s2 = blk_sum(s2, red, t);
    float inv2 = 1.f / (s2 + 1e-8f);
    for (int i = t; i < len; i += 256) a[i] *= inv2;
    __syncthreads();
}

__global__ __launch_bounds__(256)
void final_kernel(const float* __restrict__ H, const float* __restrict__ part,
                  const float* __restrict__ cnt, const float* __restrict__ log_tau,
                  const float* __restrict__ Wg1, const float* __restrict__ bg1,
                  const float* __restrict__ Wg2, const float* __restrict__ bg2,
                  const float* __restrict__ Wo,  const float* __restrict__ bo,
                  const float* __restrict__ ln_g, const float* __restrict__ ln_b,
                  const float* __restrict__ lvlw, float* __restrict__ out)
{
    __shared__ float sw[M_TOT];
    __shared__ float red[256];
    __shared__ float wcs[16], wts[128], wvs[512], wss[16];
    __shared__ float coeff[M_TOT];
    __shared__ float xc[512];       // [z, pos_pool]
    __shared__ float hb[256], gb[256], yb[256], zg[256];
    __shared__ float lw[4];

    int b = blockIdx.x;
    int t = threadIdx.x;
    const float* Hb = H + (long)b * M_TOT * DIM;
    float tau = fminf(fmaxf(expf(log_tau[0]) + 0.1f, 0.1f), 2.0f);

    if (t == 0) {
        float m = fmaxf(fmaxf(lvlw[0], lvlw[1]), fmaxf(lvlw[2], lvlw[3]));
        float e0 = expf(lvlw[0]-m), e1 = expf(lvlw[1]-m), e2 = expf(lvlw[2]-m), e3 = expf(lvlw[3]-m);
        float s = e0+e1+e2+e3;
        lw[0]=e0/s; lw[1]=e1/s; lw[2]=e2/s; lw[3]=e3/s;
    }

    // w_raw[m] = ||H[b,m]|| / tau
    int w = t >> 5, l = t & 31;
    for (int m = w; m < M_TOT; m += 8) {
        const float* hr = Hb + m * DIM;
        float s = 0.f;
        #pragma unroll
        for (int i = 0; i < 8; i++) { float x = hr[l + 32 * i]; s += x * x; }
        #pragma unroll
        for (int o = 16; o > 0; o >>= 1) s += __shfl_xor_sync(0xffffffffu, s, o);
        if (l == 0) sw[m] = sqrtf(s) / tau;
    }
    __syncthreads();

    // hierarchy
    if (t < 16) wcs[t] = sw[t];
    __syncthreads();
    softmax_sparsify(wcs, 16, 0.1f, red, t);
    if (t < 128) wts[t] = sw[16 + t] * wcs[t >> 3];
    __syncthreads();
    softmax_sparsify(wts, 128, 0.05f, red, t);
    for (int i = t; i < 512; i += 256) wvs[i] = sw[144 + i] * wts[i >> 2];
    __syncthreads();
    softmax_sparsify(wvs, 512, 0.025f, red, t);
    if (t < 16) wss[t] = sw[656 + t];
    __syncthreads();
    softmax_sparsify(wss, 16, 0.1f, red, t);

    for (int i = t; i < M_TOT; i += 256) {
        float c;
        if (i < 16)       c = lw[0] * wcs[i];
        else if (i < 144) c = lw[1] * wts[i - 16];
        else if (i < 656) c = lw[2] * wvs[i - 144];
        else              c = lw[3] * wss[i - 656];
        coeff[i] = c;
    }
    __syncthreads();

    // z[d] = sum_m coeff[m] * H[m][d]
    float z = 0.f;
    for (int m = 0; m < M_TOT; m++) z += coeff[m] * Hb[m * DIM + t];
    xc[t] = z;

    // pos_pool
    float pp = 0.f, cc = 0.f;
    #pragma unroll
    for (int s = 0; s < 16; s++) {
        pp += part[((long)b * 16 + s) * DIM + t];
        cc += cnt[b * 16 + s];
    }
    xc[256 + t] = pp / (cc + 1e-8f);
    __syncthreads();

    // h = gelu(Wg1 @ xc + bg1), warp per row
    for (int j = w; j < 256; j += 8) {
        const float* wr = Wg1 + j * 512;
        float s = 0.f;
        #pragma unroll
        for (int i = 0; i < 16; i++) s += wr[l + 32 * i] * xc[l + 32 * i];
        #pragma unroll
        for (int o = 16; o > 0; o >>= 1) s += __shfl_xor_sync(0xffffffffu, s, o);
        if (l == 0) {
            float x = s + bg1[j];
            hb[j] = 0.5f * x * (1.0f + erff(x * 0.70710678118654752f));
        }
    }
    __syncthreads();

    // gate = sigmoid(Wg2 @ h + bg2)
    for (int j = w; j < 256; j += 8) {
        const float* wr = Wg2 + j * 256;
        float s = 0.f;
        #pragma unroll
        for (int i = 0; i < 8; i++) s += wr[l + 32 * i] * hb[l + 32 * i];
        #pragma unroll
        for (int o = 16; o > 0; o >>= 1) s += __shfl_xor_sync(0xffffffffu, s, o);
        if (l == 0) gb[j] = 1.0f / (1.0f + expf(-(s + bg2[j])));
    }
    __syncthreads();

    zg[t] = xc[t] * gb[t];
    __syncthreads();

    // y = Wo @ zg + bo
    for (int j = w; j < 256; j += 8) {
        const float* wr = Wo + j * 256;
        float s = 0.f;
        #pragma unroll
        for (int i = 0; i < 8; i++) s += wr[l + 32 * i] * zg[l + 32 * i];
        #pragma unroll
        for (int o = 16; o > 0; o >>= 1) s += __shfl_xor_sync(0xffffffffu, s, o);
        if (l == 0) yb[j] = s + bo[j];
    }
    __syncthreads();

    float y = yb[t];
    float mu = blk_sum(y, red, t) * (1.0f / 256.0f);
    float d0 = y - mu;
    float var = blk_sum(d0 * d0, red, t) * (1.0f / 256.0f);
    out[(long)b * DIM + t] = d0 * rsqrtf(var + 1e-5f) * ln_g[t] + ln_b[t];
}

// ---------------- launch ----------------
extern "C" void kernel_launch(void* const* d_in, const int* in_sizes, int n_in,
                              void* d_out, int out_size)
{
    const float* X    = (const float*)d_in[0];
    const float* pos  = (const float*)d_in[1];
    const unsigned char* mask = (const unsigned char*)d_in[2];
    const float* cat  = (const float*)d_in[3];
    const float* typ  = (const float*)d_in[4];
    const float* var  = (const float*)d_in[5];
    const float* sp   = (const float*)d_in[6];
    const float* log_tau = (const float*)d_in[7];
    const float* Wk   = (const float*)d_in[8];
    const float* bk   = (const float*)d_in[9];
    const float* Wcat = (const float*)d_in[10];
    const float* bcat = (const float*)d_in[11];
    const float* Wtype= (const float*)d_in[12];
    const float* btype= (const float*)d_in[13];
    const float* Wvar = (const float*)d_in[14];
    const float* bvar = (const float*)d_in[15];
    const float* Wsp  = (const float*)d_in[16];
    const float* bsp  = (const float*)d_in[17];
    const float* Wg1  = (const float*)d_in[18];
    const float* bg1  = (const float*)d_in[19];
    const float* Wg2  = (const float*)d_in[20];
    const float* bg2  = (const float*)d_in[21];
    const float* Wo   = (const float*)d_in[22];
    const float* bo   = (const float*)d_in[23];
    const float* ln_g = (const float*)d_in[24];
    const float* ln_b = (const float*)d_in[25];
    const float* lvlw = (const float*)d_in[26];
    float* out = (float*)d_out;

    float *Qp, *cvec, *S, *H, *part, *cnt;
    cudaGetSymbolAddress((void**)&Qp,   g_Qp);
    cudaGetSymbolAddress((void**)&cvec, g_c);
    cudaGetSymbolAddress((void**)&S,    g_S);
    cudaGetSymbolAddress((void**)&H,    g_H);
    cudaGetSymbolAddress((void**)&part, g_part);
    cudaGetSymbolAddress((void**)&cnt,  g_cnt);

    // 1) Q' and c
    prep_q<<<M_TOT, 256>>>(cat, typ, var, sp, Wcat, bcat, Wtype, btype,
                           Wvar, bvar, Wsp, bsp, Wk, bk, Qp, cvec);

    // 2) logits: S[b][m][n] = clip(Qp[m].X[b][n] + c[m]) with mask
    {
        dim3 grid(NTOK / 128, (M_TOT + 127) / 128, BATCH);
        gemm_kernel<true, true><<<grid, 256>>>(
            Qp, X, S, M_TOT, NTOK, DIM,
            DIM, DIM, NTOK,
            0L, (long)NTOK * DIM, (long)M_TOT * NTOK,
            cvec, mask);
    }

    // 3) softmax rows
    softmax_rows<<<BATCH * M_TOT, 256>>>(S);

    // 4) H = G @ X
    {
        dim3 grid(DIM / 128, (M_TOT + 127) / 128, BATCH);
        gemm_kernel<false, false><<<grid, 256>>>(
            S, X, H, M_TOT, DIM, NTOK,
            NTOK, DIM, DIM,
            (long)M_TOT * NTOK, (long)NTOK * DIM, (long)M_TOT * DIM,
            (const float*)0, (const unsigned char*)0);
    }

    // 5) position pooling partials
    {
        dim3 grid(16, BATCH);
        pospool_partial<<<grid, 256>>>(pos, mask, part, cnt);
    }

    // 6) per-batch tail
    final_kernel<<<BATCH, 256>>>(H, part, cnt, log_tau,
                                 Wg1, bg1, Wg2, bg2, Wo, bo,
                                 ln_g, ln_b, lvlw, out);
}

// round 3
// speedup vs baseline: 2.3393x; 2.3393x over previous
#include <cuda_runtime.h>
#include <cuda_bf16.h>
#include <math.h>

#define BATCH 32
#define NTOK  4096
#define DIM   256
#define M_TOT 672

// ---------------- scratch ----------------
__device__ __nv_bfloat16 g_Qh[M_TOT * DIM];
__device__ float         g_c [M_TOT];
__device__ __nv_bfloat16 g_S [(long)BATCH * M_TOT * NTOK];
__device__ __nv_bfloat16 g_Gh[(long)BATCH * M_TOT * NTOK];
__device__ __nv_bfloat16 g_Gl[(long)BATCH * M_TOT * NTOK];
__device__ __nv_bfloat16 g_Xh[(long)BATCH * NTOK * DIM];
__device__ __nv_bfloat16 g_Xl[(long)BATCH * NTOK * DIM];
__device__ float g_H[BATCH * M_TOT * DIM];
__device__ float g_part[BATCH * 16 * DIM];
__device__ float g_cnt [BATCH * 16];

// ---------------- helpers ----------------
__device__ __forceinline__ unsigned sm_u32(const void* p) {
    return (unsigned)__cvta_generic_to_shared(p);
}
__device__ __forceinline__ void ldsm4(unsigned r[4], unsigned addr) {
    asm volatile("ldmatrix.sync.aligned.m8n8.x4.shared.b16 {%0,%1,%2,%3},[%4];"
                 : "=r"(r[0]), "=r"(r[1]), "=r"(r[2]), "=r"(r[3]) : "r"(addr));
}
__device__ __forceinline__ void ldsm2(unsigned r[2], unsigned addr) {
    asm volatile("ldmatrix.sync.aligned.m8n8.x2.shared.b16 {%0,%1},[%2];"
                 : "=r"(r[0]), "=r"(r[1]) : "r"(addr));
}
__device__ __forceinline__ void ldsm2t(unsigned r[2], unsigned addr) {
    asm volatile("ldmatrix.sync.aligned.m8n8.x2.trans.shared.b16 {%0,%1},[%2];"
                 : "=r"(r[0]), "=r"(r[1]) : "r"(addr));
}
__device__ __forceinline__ void mma16816(float c[4], const unsigned a[4], const unsigned b[2]) {
    asm volatile(
        "mma.sync.aligned.m16n8k16.row.col.f32.bf16.bf16.f32 "
        "{%0,%1,%2,%3},{%4,%5,%6,%7},{%8,%9},{%0,%1,%2,%3};"
        : "+f"(c[0]), "+f"(c[1]), "+f"(c[2]), "+f"(c[3])
        : "r"(a[0]), "r"(a[1]), "r"(a[2]), "r"(a[3]), "r"(b[0]), "r"(b[1]));
}
__device__ __forceinline__ unsigned pack_bf2(float a, float b) {
    __nv_bfloat162 t;
    t.x = __float2bfloat16(a); t.y = __float2bfloat16(b);
    return *(unsigned*)&t;
}

// ---------------- X -> hi/lo bf16 ----------------
__global__ __launch_bounds__(256)
void convert_x(const float4* __restrict__ X, unsigned* __restrict__ Xh,
               unsigned* __restrict__ Xl)
{
    long i = (long)blockIdx.x * 256 + threadIdx.x;   // over float4s
    float4 v = X[i];
    float hx = __bfloat162float(__float2bfloat16(v.x));
    float hy = __bfloat162float(__float2bfloat16(v.y));
    float hz = __bfloat162float(__float2bfloat16(v.z));
    float hw = __bfloat162float(__float2bfloat16(v.w));
    uint2 ho, lo;
    ho.x = pack_bf2(v.x, v.y);       ho.y = pack_bf2(v.z, v.w);
    lo.x = pack_bf2(v.x - hx, v.y - hy); lo.y = pack_bf2(v.z - hz, v.w - hw);
    *(uint2*)(Xh + i * 2) = ho;
    *(uint2*)(Xl + i * 2) = lo;
}

// ---------------- prep: Qh = bf16((codes@Wq^T+bq)@Wk / 16), c = q.bk/16 ----------------
__global__ __launch_bounds__(256)
void prep_q(const float* __restrict__ cat, const float* __restrict__ typ,
            const float* __restrict__ var, const float* __restrict__ sp,
            const float* __restrict__ Wcat, const float* __restrict__ bcat,
            const float* __restrict__ Wtype, const float* __restrict__ btype,
            const float* __restrict__ Wvar, const float* __restrict__ bvar,
            const float* __restrict__ Wsp, const float* __restrict__ bsp,
            const float* __restrict__ Wk, const float* __restrict__ bk,
            __nv_bfloat16* __restrict__ Qh, float* __restrict__ cvec)
{
    int m = blockIdx.x;
    const float* codes; const float* Wq; const float* bq;
    if (m < 16)       { codes = cat + m * DIM;         Wq = Wcat;  bq = bcat; }
    else if (m < 144) { codes = typ + (m - 16) * DIM;  Wq = Wtype; bq = btype; }
    else if (m < 656) { codes = var + (m - 144) * DIM; Wq = Wvar;  bq = bvar; }
    else              { codes = sp + (m - 656) * DIM;  Wq = Wsp;   bq = bsp; }

    __shared__ float cs[DIM], qs[DIM], red[256];
    int t = threadIdx.x;
    cs[t] = codes[t];
    __syncthreads();

    int w = t >> 5, l = t & 31;
    for (int j = w; j < DIM; j += 8) {
        const float* wr = Wq + j * DIM;
        float s = 0.f;
        #pragma unroll
        for (int i = 0; i < 8; i++) s += wr[l + 32 * i] * cs[l + 32 * i];
        #pragma unroll
        for (int o = 16; o > 0; o >>= 1) s += __shfl_xor_sync(0xffffffffu, s, o);
        if (l == 0) qs[j] = s + bq[j];
    }
    __syncthreads();

    float a = 0.f;
    for (int j = 0; j < DIM; j++) a += qs[j] * Wk[j * DIM + t];
    Qh[m * DIM + t] = __float2bfloat16(a * 0.0625f);

    red[t] = qs[t] * bk[t];
    __syncthreads();
    for (int s = 128; s > 0; s >>= 1) { if (t < s) red[t] += red[t + s]; __syncthreads(); }
    if (t == 0) cvec[m] = red[0] * 0.0625f;
}

// ---------------- logits: S[b][m][n] = bf16(clip(Qh[m].Xh[b][n] + c[m])) ----------------
__global__ __launch_bounds__(256)
void logits_mma(const __nv_bfloat16* __restrict__ Qh,
                const __nv_bfloat16* __restrict__ Xh,
                __nv_bfloat16* __restrict__ S,
                const float* __restrict__ cvec,
                const unsigned char* __restrict__ mask)
{
    const int SK = 40;
    __shared__ __nv_bfloat16 sA[128 * SK];
    __shared__ __nv_bfloat16 sB[128 * SK];

    int b = blockIdx.z;
    int m0 = blockIdx.y * 128, n0 = blockIdx.x * 128;
    const __nv_bfloat16* Xb = Xh + (long)b * NTOK * DIM;
    int t = threadIdx.x, lane = t & 31, w = t >> 5;
    int wm = (w >> 2) * 64, wn = (w & 3) * 32;

    uint4 ra[2], rb[2];
    auto gload = [&](int kt) {
        #pragma unroll
        for (int i = 0; i < 2; i++) {
            int c = t + i * 256;
            int row = c >> 2, kc = (c & 3) * 8;
            int gm = m0 + row;
            ra[i] = make_uint4(0u, 0u, 0u, 0u);
            if (gm < M_TOT) ra[i] = *(const uint4*)(Qh + gm * DIM + kt * 32 + kc);
            rb[i] = *(const uint4*)(Xb + (long)(n0 + row) * DIM + kt * 32 + kc);
        }
    };
    auto sstore = [&]() {
        #pragma unroll
        for (int i = 0; i < 2; i++) {
            int c = t + i * 256;
            int row = c >> 2, kc = (c & 3) * 8;
            *(uint4*)(sA + row * SK + kc) = ra[i];
            *(uint4*)(sB + row * SK + kc) = rb[i];
        }
    };

    int l15 = lane & 15;
    unsigned aBase = sm_u32(sA + (wm + l15) * SK + (lane >> 4) * 8);
    unsigned bBase = sm_u32(sB + (wn + (l15 & 7)) * SK + (l15 >> 3) * 8);

    float acc[4][4][4] = {};
    gload(0);
    for (int kt = 0; kt < 8; kt++) {
        __syncthreads();
        sstore();
        __syncthreads();
        if (kt < 7) gload(kt + 1);
        #pragma unroll
        for (int ks = 0; ks < 2; ks++) {
            unsigned a[4][4], bf[4][2];
            #pragma unroll
            for (int mi = 0; mi < 4; mi++) ldsm4(a[mi], aBase + (unsigned)(mi * 16 * SK + ks * 16) * 2u);
            #pragma unroll
            for (int ni = 0; ni < 4; ni++) ldsm2(bf[ni], bBase + (unsigned)(ni * 8 * SK + ks * 16) * 2u);
            #pragma unroll
            for (int mi = 0; mi < 4; mi++)
                #pragma unroll
                for (int ni = 0; ni < 4; ni++) mma16816(acc[mi][ni], a[mi], bf[ni]);
        }
    }

    const unsigned char* mrow = mask + (long)b * NTOK;
    #pragma unroll
    for (int mi = 0; mi < 4; mi++) {
        #pragma unroll
        for (int r = 0; r < 2; r++) {
            int gm = m0 + wm + mi * 16 + (lane >> 2) + r * 8;
            if (gm >= M_TOT) continue;
            float cv = cvec[gm];
            __nv_bfloat16* srow = S + ((long)b * M_TOT + gm) * NTOK;
            #pragma unroll
            for (int ni = 0; ni < 4; ni++) {
                int col = n0 + wn + ni * 8 + (lane & 3) * 2;
                float x0 = acc[mi][ni][r * 2 + 0] + cv;
                float x1 = acc[mi][ni][r * 2 + 1] + cv;
                x0 = fminf(fmaxf(x0, -50.f), 50.f);
                x1 = fminf(fmaxf(x1, -50.f), 50.f);
                if (!mrow[col])     x0 = -50.f;
                if (!mrow[col + 1]) x1 = -50.f;
                __nv_bfloat162 v;
                v.x = __float2bfloat16(x0); v.y = __float2bfloat16(x1);
                *(__nv_bfloat162*)(srow + col) = v;
            }
        }
    }
}

// ---------------- softmax rows -> Gh/Gl (hi/lo bf16) ----------------
__global__ __launch_bounds__(256)
void softmax_rows(const __nv_bfloat16* __restrict__ S,
                  __nv_bfloat16* __restrict__ Gh, __nv_bfloat16* __restrict__ Gl)
{
    long row = blockIdx.x;
    const __nv_bfloat162* p = (const __nv_bfloat162*)(S + row * (long)NTOK);
    __nv_bfloat162* gh = (__nv_bfloat162*)(Gh + row * (long)NTOK);
    __nv_bfloat162* gl = (__nv_bfloat162*)(Gl + row * (long)NTOK);
    int t = threadIdx.x;
    float v[16];
    float mx = -1e30f;
    #pragma unroll
    for (int i = 0; i < 8; i++) {
        __nv_bfloat162 x = p[t + 256 * i];
        v[2 * i]     = __bfloat162float(x.x);
        v[2 * i + 1] = __bfloat162float(x.y);
        mx = fmaxf(mx, fmaxf(v[2 * i], v[2 * i + 1]));
    }
    __shared__ float red[256];
    red[t] = mx; __syncthreads();
    for (int s = 128; s > 0; s >>= 1) { if (t < s) red[t] = fmaxf(red[t], red[t + s]); __syncthreads(); }
    mx = red[0]; __syncthreads();
    float sum = 0.f;
    #pragma unroll
    for (int i = 0; i < 16; i++) { v[i] = expf(v[i] - mx); sum += v[i]; }
    red[t] = sum; __syncthreads();
    for (int s = 128; s > 0; s >>= 1) { if (t < s) red[t] += red[t + s]; __syncthreads(); }
    float inv = 1.0f / red[0];
    #pragma unroll
    for (int i = 0; i < 8; i++) {
        float g0 = v[2 * i] * inv, g1 = v[2 * i + 1] * inv;
        __nv_bfloat162 h, l;
        h.x = __float2bfloat16(g0); h.y = __float2bfloat16(g1);
        l.x = __float2bfloat16(g0 - __bfloat162float(h.x));
        l.y = __float2bfloat16(g1 - __bfloat162float(h.y));
        gh[t + 256 * i] = h;
        gl[t + 256 * i] = l;
    }
}

// ---------------- H = G @ X  (split-3 bf16) ----------------
__global__ __launch_bounds__(256)
void h_mma(const __nv_bfloat16* __restrict__ Gh, const __nv_bfloat16* __restrict__ Gl,
           const __nv_bfloat16* __restrict__ Xh, const __nv_bfloat16* __restrict__ Xl,
           float* __restrict__ H)
{
    const int SK = 40, SN = 136;
    __shared__ __nv_bfloat16 sAh[128 * SK];
    __shared__ __nv_bfloat16 sAl[128 * SK];
    __shared__ __nv_bfloat16 sBh[32 * SN];
    __shared__ __nv_bfloat16 sBl[32 * SN];

    int b = blockIdx.z;
    int m0 = blockIdx.y * 128, n0 = blockIdx.x * 128;
    const __nv_bfloat16* Ghb = Gh + (long)b * M_TOT * NTOK;
    const __nv_bfloat16* Glb = Gl + (long)b * M_TOT * NTOK;
    const __nv_bfloat16* Xhb = Xh + (long)b * NTOK * DIM;
    const __nv_bfloat16* Xlb = Xl + (long)b * NTOK * DIM;
    int t = threadIdx.x, lane = t & 31, w = t >> 5;
    int wm = (w >> 2) * 64, wn = (w & 3) * 32;

    uint4 rah[2], ral[2], rbh[2], rbl[2];
    auto gload = [&](int kt) {
        #pragma unroll
        for (int i = 0; i < 2; i++) {
            int c = t + i * 256;
            {
                int row = c >> 2, kc = (c & 3) * 8;
                int gm = m0 + row;
                rah[i] = make_uint4(0u, 0u, 0u, 0u);
                ral[i] = rah[i];
                if (gm < M_TOT) {
                    long off = (long)gm * NTOK + kt * 32 + kc;
                    rah[i] = *(const uint4*)(Ghb + off);
                    ral[i] = *(const uint4*)(Glb + off);
                }
            }
            {
                int kr = c >> 4, nc = (c & 15) * 8;
                long off = (long)(kt * 32 + kr) * DIM + n0 + nc;
                rbh[i] = *(const uint4*)(Xhb + off);
                rbl[i] = *(const uint4*)(Xlb + off);
            }
        }
    };
    auto sstore = [&]() {
        #pragma unroll
        for (int i = 0; i < 2; i++) {
            int c = t + i * 256;
            int row = c >> 2, kc = (c & 3) * 8;
            *(uint4*)(sAh + row * SK + kc) = rah[i];
            *(uint4*)(sAl + row * SK + kc) = ral[i];
            int kr = c >> 4, nc = (c & 15) * 8;
            *(uint4*)(sBh + kr * SN + nc) = rbh[i];
            *(uint4*)(sBl + kr * SN + nc) = rbl[i];
        }
    };

    int l15 = lane & 15;
    unsigned ahB = sm_u32(sAh + (wm + l15) * SK + (lane >> 4) * 8);
    unsigned alB = sm_u32(sAl + (wm + l15) * SK + (lane >> 4) * 8);
    unsigned bhB = sm_u32(sBh + l15 * SN + wn);
    unsigned blB = sm_u32(sBl + l15 * SN + wn);

    float acc[4][4][4] = {};
    gload(0);
    for (int kt = 0; kt < NTOK / 32; kt++) {
        __syncthreads();
        sstore();
        __syncthreads();
        if (kt < NTOK / 32 - 1) gload(kt + 1);
        #pragma unroll
        for (int ks = 0; ks < 2; ks++) {
            unsigned ah[4][4], al[4][4], bh[4][2], bl[4][2];
            #pragma unroll
            for (int mi = 0; mi < 4; mi++) ldsm4(ah[mi], ahB + (unsigned)(mi * 16 * SK + ks * 16) * 2u);
            #pragma unroll
            for (int ni = 0; ni < 4; ni++) ldsm2t(bh[ni], bhB + (unsigned)(ks * 16 * SN) * 2u + (unsigned)ni * 16u);
            #pragma unroll
            for (int mi = 0; mi < 4; mi++)
                #pragma unroll
                for (int ni = 0; ni < 4; ni++) mma16816(acc[mi][ni], ah[mi], bh[ni]);
            #pragma unroll
            for (int ni = 0; ni < 4; ni++) ldsm2t(bl[ni], blB + (unsigned)(ks * 16 * SN) * 2u + (unsigned)ni * 16u);
            #pragma unroll
            for (int mi = 0; mi < 4; mi++)
                #pragma unroll
                for (int ni = 0; ni < 4; ni++) mma16816(acc[mi][ni], ah[mi], bl[ni]);
            #pragma unroll
            for (int mi = 0; mi < 4; mi++) ldsm4(al[mi], alB + (unsigned)(mi * 16 * SK + ks * 16) * 2u);
            #pragma unroll
            for (int mi = 0; mi < 4; mi++)
                #pragma unroll
                for (int ni = 0; ni < 4; ni++) mma16816(acc[mi][ni], al[mi], bh[ni]);
        }
    }

    #pragma unroll
    for (int mi = 0; mi < 4; mi++) {
        #pragma unroll
        for (int r = 0; r < 2; r++) {
            int gm = m0 + wm + mi * 16 + (lane >> 2) + r * 8;
            if (gm >= M_TOT) continue;
            float* hrow = H + ((long)b * M_TOT + gm) * DIM;
            #pragma unroll
            for (int ni = 0; ni < 4; ni++) {
                int col = n0 + wn + ni * 8 + (lane & 3) * 2;
                *(float2*)(hrow + col) =
                    make_float2(acc[mi][ni][r * 2 + 0], acc[mi][ni][r * 2 + 1]);
            }
        }
    }
}

// ---------------- masked position pooling partials ----------------
__global__ __launch_bounds__(256)
void pospool_partial(const float* __restrict__ pos, const unsigned char* __restrict__ mask,
                     float* __restrict__ part, float* __restrict__ cnt)
{
    int s = blockIdx.x, b = blockIdx.y;
    int t = threadIdx.x;
    const float* P = pos + ((long)b * NTOK + s * 256) * DIM;
    const unsigned char* M = mask + (long)b * NTOK + s * 256;
    float acc = 0.f, c = 0.f;
    for (int n = 0; n < 256; n++) {
        float mm = M[n] ? 1.f : 0.f;
        c += mm;
        acc += mm * P[(long)n * DIM + t];
    }
    part[((long)b * 16 + s) * DIM + t] = acc;
    if (t == 0) cnt[b * 16 + s] = c;
}

// ---------------- per-batch tail ----------------
__device__ __forceinline__ float blk_sum(float v, float* red, int t)
{
    __syncthreads();
    red[t] = v; __syncthreads();
    for (int s = 128; s > 0; s >>= 1) { if (t < s) red[t] += red[t + s]; __syncthreads(); }
    float r = red[0]; __syncthreads();
    return r;
}
__device__ __forceinline__ float blk_max(float v, float* red, int t)
{
    __syncthreads();
    red[t] = v; __syncthreads();
    for (int s = 128; s > 0; s >>= 1) { if (t < s) red[t] = fmaxf(red[t], red[t + s]); __syncthreads(); }
    float r = red[0]; __syncthreads();
    return r;
}
__device__ void softmax_sparsify(float* a, int len, float thr, float* red, int t)
{
    float m = -1e30f;
    for (int i = t; i < len; i += 256) m = fmaxf(m, a[i]);
    m = blk_max(m, red, t);
    float s = 0.f;
    for (int i = t; i < len; i += 256) { float e = expf(a[i] - m); a[i] = e; s += e; }
    s = blk_sum(s, red, t);
    float inv = 1.f / s;
    float s2 = 0.f;
    for (int i = t; i < len; i += 256) { float p = a[i] * inv; p = (p > thr) ? p : 0.f; a[i] = p; s2 += p; }
    s2 = blk_sum(s2, red, t);
    float inv2 = 1.f / (s2 + 1e-8f);
    for (int i = t; i < len; i += 256) a[i] *= inv2;
    __syncthreads();
}

__global__ __launch_bounds__(256)
void final_kernel(const float* __restrict__ H, const float* __restrict__ part,
                  const float* __restrict__ cnt, const float* __restrict__ log_tau,
                  const float* __restrict__ Wg1, const float* __restrict__ bg1,
                  const float* __restrict__ Wg2, const float* __restrict__ bg2,
                  const float* __restrict__ Wo,  const float* __restrict__ bo,
                  const float* __restrict__ ln_g, const float* __restrict__ ln_b,
                  const float* __restrict__ lvlw, float* __restrict__ out)
{
    __shared__ float sw[M_TOT];
    __shared__ float red[256];
    __shared__ float wcs[16], wts[128], wvs[512], wss[16];
    __shared__ float coeff[M_TOT];
    __shared__ float xc[512];
    __shared__ float hb[256], gb[256], yb[256], zg[256];
    __shared__ float lw[4];

    int b = blockIdx.x;
    int t = threadIdx.x;
    const float* Hb = H + (long)b * M_TOT * DIM;
    float tau = fminf(fmaxf(expf(log_tau[0]) + 0.1f, 0.1f), 2.0f);

    if (t == 0) {
        float m = fmaxf(fmaxf(lvlw[0], lvlw[1]), fmaxf(lvlw[2], lvlw[3]));
        float e0 = expf(lvlw[0]-m), e1 = expf(lvlw[1]-m), e2 = expf(lvlw[2]-m), e3 = expf(lvlw[3]-m);
        float s = e0+e1+e2+e3;
        lw[0]=e0/s; lw[1]=e1/s; lw[2]=e2/s; lw[3]=e3/s;
    }

    int w = t >> 5, l = t & 31;
    for (int m = w; m < M_TOT; m += 8) {
        const float* hr = Hb + m * DIM;
        float s = 0.f;
        #pragma unroll
        for (int i = 0; i < 8; i++) { float x = hr[l + 32 * i]; s += x * x; }
        #pragma unroll
        for (int o = 16; o > 0; o >>= 1) s += __shfl_xor_sync(0xffffffffu, s, o);
        if (l == 0) sw[m] = sqrtf(s) / tau;
    }
    __syncthreads();

    if (t < 16) wcs[t] = sw[t];
    __syncthreads();
    softmax_sparsify(wcs, 16, 0.1f, red, t);
    if (t < 128) wts[t] = sw[16 + t] * wcs[t >> 3];
    __syncthreads();
    softmax_sparsify(wts, 128, 0.05f, red, t);
    for (int i = t; i < 512; i += 256) wvs[i] = sw[144 + i] * wts[i >> 2];
    __syncthreads();
    softmax_sparsify(wvs, 512, 0.025f, red, t);
    if (t < 16) wss[t] = sw[656 + t];
    __syncthreads();
    softmax_sparsify(wss, 16, 0.1f, red, t);

    for (int i = t; i < M_TOT; i += 256) {
        float c;
        if (i < 16)       c = lw[0] * wcs[i];
        else if (i < 144) c = lw[1] * wts[i - 16];
        else if (i < 656) c = lw[2] * wvs[i - 144];
        else              c = lw[3] * wss[i - 656];
        coeff[i] = c;
    }
    __syncthreads();

    float z = 0.f;
    for (int m = 0; m < M_TOT; m++) z += coeff[m] * Hb[m * DIM + t];
    xc[t] = z;

    float pp = 0.f, cc = 0.f;
    #pragma unroll
    for (int s = 0; s < 16; s++) {
        pp += part[((long)b * 16 + s) * DIM + t];
        cc += cnt[b * 16 + s];
    }
    xc[256 + t] = pp / (cc + 1e-8f);
    __syncthreads();

    for (int j = w; j < 256; j += 8) {
        const float* wr = Wg1 + j * 512;
        float s = 0.f;
        #pragma unroll
        for (int i = 0; i < 16; i++) s += wr[l + 32 * i] * xc[l + 32 * i];
        #pragma unroll
        for (int o = 16; o > 0; o >>= 1) s += __shfl_xor_sync(0xffffffffu, s, o);
        if (l == 0) {
            float x = s + bg1[j];
            hb[j] = 0.5f * x * (1.0f + erff(x * 0.70710678118654752f));
        }
    }
    __syncthreads();

    for (int j = w; j < 256; j += 8) {
        const float* wr = Wg2 + j * 256;
        float s = 0.f;
        #pragma unroll
        for (int i = 0; i < 8; i++) s += wr[l + 32 * i] * hb[l + 32 * i];
        #pragma unroll
        for (int o = 16; o > 0; o >>= 1) s += __shfl_xor_sync(0xffffffffu, s, o);
        if (l == 0) gb[j] = 1.0f / (1.0f + expf(-(s + bg2[j])));
    }
    __syncthreads();

    zg[t] = xc[t] * gb[t];
    __syncthreads();

    for (int j = w; j < 256; j += 8) {
        const float* wr = Wo + j * 256;
        float s = 0.f;
        #pragma unroll
        for (int i = 0; i < 8; i++) s += wr[l + 32 * i] * zg[l + 32 * i];
        #pragma unroll
        for (int o = 16; o > 0; o >>= 1) s += __shfl_xor_sync(0xffffffffu, s, o);
        if (l == 0) yb[j] = s + bo[j];
    }
    __syncthreads();

    float y = yb[t];
    float mu = blk_sum(y, red, t) * (1.0f / 256.0f);
    float d0 = y - mu;
    float var = blk_sum(d0 * d0, red, t) * (1.0f / 256.0f);
    out[(long)b * DIM + t] = d0 * rsqrtf(var + 1e-5f) * ln_g[t] + ln_b[t];
}

// ---------------- launch ----------------
extern "C" void kernel_launch(void* const* d_in, const int* in_sizes, int n_in,
                              void* d_out, int out_size)
{
    const float* X    = (const float*)d_in[0];
    const float* pos  = (const float*)d_in[1];
    const unsigned char* mask = (const unsigned char*)d_in[2];
    const float* cat  = (const float*)d_in[3];
    const float* typ  = (const float*)d_in[4];
    const float* var  = (const float*)d_in[5];
    const float* sp   = (const float*)d_in[6];
    const float* log_tau = (const float*)d_in[7];
    const float* Wk   = (const float*)d_in[8];
    const float* bk   = (const float*)d_in[9];
    const float* Wcat = (const float*)d_in[10];
    const float* bcat = (const float*)d_in[11];
    const float* Wtype= (const float*)d_in[12];
    const float* btype= (const float*)d_in[13];
    const float* Wvar = (const float*)d_in[14];
    const float* bvar = (const float*)d_in[15];
    const float* Wsp  = (const float*)d_in[16];
    const float* bsp  = (const float*)d_in[17];
    const float* Wg1  = (const float*)d_in[18];
    const float* bg1  = (const float*)d_in[19];
    const float* Wg2  = (const float*)d_in[20];
    const float* bg2  = (const float*)d_in[21];
    const float* Wo   = (const float*)d_in[22];
    const float* bo   = (const float*)d_in[23];
    const float* ln_g = (const float*)d_in[24];
    const float* ln_b = (const float*)d_in[25];
    const float* lvlw = (const float*)d_in[26];
    float* out = (float*)d_out;

    __nv_bfloat16 *Qh, *S, *Gh, *Gl, *Xh, *Xl;
    float *cvec, *H, *part, *cnt;
    cudaGetSymbolAddress((void**)&Qh,   g_Qh);
    cudaGetSymbolAddress((void**)&cvec, g_c);
    cudaGetSymbolAddress((void**)&S,    g_S);
    cudaGetSymbolAddress((void**)&Gh,   g_Gh);
    cudaGetSymbolAddress((void**)&Gl,   g_Gl);
    cudaGetSymbolAddress((void**)&Xh,   g_Xh);
    cudaGetSymbolAddress((void**)&Xl,   g_Xl);
    cudaGetSymbolAddress((void**)&H,    g_H);
    cudaGetSymbolAddress((void**)&part, g_part);
    cudaGetSymbolAddress((void**)&cnt,  g_cnt);

    // 1) X -> hi/lo bf16
    {
        long n4 = (long)BATCH * NTOK * DIM / 4;
        convert_x<<<(unsigned)(n4 / 256), 256>>>((const float4*)X,
                                                 (unsigned*)Xh, (unsigned*)Xl);
    }

    // 2) Q' and c
    prep_q<<<M_TOT, 256>>>(cat, typ, var, sp, Wcat, bcat, Wtype, btype,
                           Wvar, bvar, Wsp, bsp, Wk, bk, Qh, cvec);

    // 3) logits (bf16 tensor-core GEMM, fused epilogue)
    {
        dim3 grid(NTOK / 128, (M_TOT + 127) / 128, BATCH);
        logits_mma<<<grid, 256>>>(Qh, Xh, S, cvec, mask);
    }

    // 4) softmax -> Gh/Gl
    softmax_rows<<<BATCH * M_TOT, 256>>>(S, Gh, Gl);

    // 5) H = G @ X (split-3 bf16 tensor-core GEMM)
    {
        dim3 grid(DIM / 128, (M_TOT + 127) / 128, BATCH);
        h_mma<<<grid, 256>>>(Gh, Gl, Xh, Xl, H);
    }

    // 6) position pooling partials
    {
        dim3 grid(16, BATCH);
        pospool_partial<<<grid, 256>>>(pos, mask, part, cnt);
    }

    // 7) per-batch tail
    final_kernel<<<BATCH, 256>>>(H, part, cnt, log_tau,
                                 Wg1, bg1, Wg2, bg2, Wo, bo,
                                 ln_g, ln_b, lvlw, out);
}